// round 17
// baseline (speedup 1.0000x reference)
#include <cuda_runtime.h>
#include <cuda_fp16.h>
#include <cstdint>

// ---------------- scratch (static device arrays; no cudaMalloc) -------------
__device__ __align__(16) __half g_Xh[4194304], g_Xl[4194304];
__device__ __align__(16) __half g_Wh[4][1048576];                // [n][k] fp16
__device__ __align__(16) __half g_Q16[4194304];                  // [bh][s][64]
__device__ __align__(16) __half g_K16[4194304], g_V16[4194304];  // [bh][s][64]
__device__ __align__(16) __half g_Ch[4194304], g_Cl[4194304];    // [m][1024]
__device__ float g_bias[16 * 4096];

// ---------------- helpers -----------------------------------------------------
__device__ __forceinline__ uint32_t smem_u32(const void* p) {
    uint32_t a;
    asm("{ .reg .u64 t; cvta.to.shared.u64 t, %1; cvt.u32.u64 %0, t; }" : "=r"(a) : "l"(p));
    return a;
}
__device__ __forceinline__ uint32_t swz(uint32_t off) { return off ^ ((off >> 3) & 0x70); }

__device__ __forceinline__ void cpa16(uint32_t saddr, const void* g) {
    asm volatile("cp.async.cg.shared.global [%0], [%1], 16;" :: "r"(saddr), "l"(g));
}
#define CP_COMMIT() asm volatile("cp.async.commit_group;" ::: "memory")
#define CP_WAIT1()  asm volatile("cp.async.wait_group 1;" ::: "memory")
#define CP_WAIT0()  asm volatile("cp.async.wait_group 0;" ::: "memory")

__device__ __forceinline__ void ldsm4(uint32_t* r, uint32_t addr) {
    asm volatile("ldmatrix.sync.aligned.m8n8.x4.shared.b16 {%0,%1,%2,%3}, [%4];"
        : "=r"(r[0]), "=r"(r[1]), "=r"(r[2]), "=r"(r[3]) : "r"(addr));
}
__device__ __forceinline__ void ldsm4t(uint32_t* r, uint32_t addr) {
    asm volatile("ldmatrix.sync.aligned.m8n8.x4.trans.shared.b16 {%0,%1,%2,%3}, [%4];"
        : "=r"(r[0]), "=r"(r[1]), "=r"(r[2]), "=r"(r[3]) : "r"(addr));
}
__device__ __forceinline__ void mma16816h(float* d, const uint32_t* a, const uint32_t* b) {
    asm volatile("mma.sync.aligned.m16n8k16.row.col.f32.f16.f16.f32 "
        "{%0,%1,%2,%3}, {%4,%5,%6,%7}, {%8,%9}, {%0,%1,%2,%3};"
        : "+f"(d[0]), "+f"(d[1]), "+f"(d[2]), "+f"(d[3])
        : "r"(a[0]), "r"(a[1]), "r"(a[2]), "r"(a[3]), "r"(b[0]), "r"(b[1]));
}
__device__ __forceinline__ uint32_t h2(float a, float b) {
    __half2 h = __floats2half2_rn(a, b);
    return *(uint32_t*)&h;
}
__device__ __forceinline__ uint32_t pkh2(float a, float b, uint32_t& lo) {
    __half2 h = __floats2half2_rn(a, b);
    __half2 l = __floats2half2_rn(a - __half2float(__low2half(h)),
                                  b - __half2float(__high2half(h)));
    lo = *(uint32_t*)&l;
    return *(uint32_t*)&h;
}

// ---------------- prep kernels -------------------------------------------------
__global__ void bias_init(const float* __restrict__ rel_bias) {
    int d = blockIdx.x * 256 + threadIdx.x;
    if (d >= 4096) return;
    int n = -(d - 2048);
    int ret = 0;
    if (n < 0) { ret = 16; n = -n; }
    int bucket;
    if      (n <  8) bucket = n;
    else if (n < 12) bucket = 8;
    else if (n < 16) bucket = 9;
    else if (n < 23) bucket = 10;
    else if (n < 32) bucket = 11;
    else if (n < 46) bucket = 12;
    else if (n < 64) bucket = 13;
    else if (n < 91) bucket = 14;
    else             bucket = 15;
    bucket += ret;
    #pragma unroll
    for (int h = 0; h < 16; h++)
        g_bias[h * 4096 + d] = rel_bias[bucket * 16 + h];
}

__global__ void split_x(const float* __restrict__ src) {
    size_t i = ((size_t)blockIdx.x * 256 + threadIdx.x) * 4;
    float4 v = *(const float4*)(src + i);
    float x[4] = {v.x, v.y, v.z, v.w};
    #pragma unroll
    for (int j = 0; j < 4; j++) {
        __half hh = __float2half_rn(x[j]);
        g_Xh[i + j] = hh;
        g_Xl[i + j] = __float2half_rn(x[j] - __half2float(hh));
    }
}

__global__ void wsplit(const float* __restrict__ W0, const float* __restrict__ W1,
                       const float* __restrict__ W2, const float* __restrict__ W3) {
    __shared__ float tile[32][33];
    const float* W = blockIdx.z == 0 ? W0 : blockIdx.z == 1 ? W1 : blockIdx.z == 2 ? W2 : W3;
    int n0 = blockIdx.x * 32, k0 = blockIdx.y * 32;
    int tx = threadIdx.x, ty = threadIdx.y;
    #pragma unroll
    for (int j = 0; j < 4; j++)
        tile[ty + j * 8][tx] = W[(size_t)(k0 + ty + j * 8) * 1024 + n0 + tx];
    __syncthreads();
    #pragma unroll
    for (int j = 0; j < 4; j++) {
        float x = tile[tx][ty + j * 8];
        size_t o = (size_t)(n0 + ty + j * 8) * 1024 + k0 + tx;     // [n][k]
        g_Wh[blockIdx.z][o] = __float2half_rn(x);
    }
}

// ---------------- unified 128x128 fp16 2-term GEMM, 2-stage, 2 CTA/SM ----------
__global__ __launch_bounds__(512, 2) void proj_gemm(float* __restrict__ outp, int qkv) {
    extern __shared__ __align__(1024) char smx[];
    const uint32_t sb = smem_u32(smx);
    const int t = threadIdx.x, lane = t & 31, wid = t >> 5;
    const int wm = wid >> 2, wn = wid & 3;         // 4x4 warp grid, 32x32 each
    const int m0 = blockIdx.y << 7, n0 = blockIdx.x << 7;
    const int mode = qkv ? (int)blockIdx.z : 3;
    const __half* Ah = (mode == 3) ? g_Ch : g_Xh;
    const __half* Al = (mode == 3) ? g_Cl : g_Xl;
    const __half* Bh = g_Wh[mode];

    auto issue = [&](int kc) {
        const int kb = kc << 6;
        const uint32_t stb = sb + (uint32_t)(kc & 1) * 49152;
        #pragma unroll
        for (int i = 0; i < 2; i++) {
            int idx = t + (i << 9);
            int row = idx >> 3, ge = (idx & 7) << 3;
            uint32_t so = swz(row * 128 + (ge << 1));
            size_t goa = (size_t)(m0 + row) * 1024 + kb + ge;
            size_t gob = (size_t)(n0 + row) * 1024 + kb + ge;
            cpa16(stb + so,         Ah + goa);
            cpa16(stb + 16384 + so, Al + goa);
            cpa16(stb + 32768 + so, Bh + gob);
        }
        CP_COMMIT();
    };

    const uint32_t a_row = (lane & 7) + ((lane >> 3) & 1) * 8;
    const uint32_t a_kb  = (lane >> 4) * 16;
    const uint32_t b_row = (lane & 7) + (lane >> 4) * 8;
    const uint32_t b_kb  = ((lane >> 3) & 1) * 16;

    float acc[2][4][4] = {};
    issue(0);
    for (int kc = 0; kc < 16; kc++) {
        if (kc + 1 < 16) { issue(kc + 1); CP_WAIT1(); }
        else             { CP_WAIT0(); }
        __syncthreads();
        const uint32_t stb = sb + (uint32_t)(kc & 1) * 49152;
        #pragma unroll
        for (int ki = 0; ki < 4; ki++) {
            uint32_t ahf[2][4], alf[2][4], bhf[2][4];
            #pragma unroll
            for (int mi = 0; mi < 2; mi++) {
                uint32_t off = swz(((wm << 5) + (mi << 4) + a_row) * 128 + (ki << 5) + a_kb);
                ldsm4(ahf[mi], stb + off);
                ldsm4(alf[mi], stb + 16384 + off);
            }
            #pragma unroll
            for (int nh = 0; nh < 2; nh++) {
                uint32_t off = swz(((wn << 5) + (nh << 4) + b_row) * 128 + (ki << 5) + b_kb);
                ldsm4(bhf[nh], stb + 32768 + off);
            }
            #pragma unroll
            for (int mi = 0; mi < 2; mi++)
                #pragma unroll
                for (int ni = 0; ni < 4; ni++)
                    mma16816h(acc[mi][ni], ahf[mi], &bhf[ni >> 1][(ni & 1) << 1]);
            #pragma unroll
            for (int mi = 0; mi < 2; mi++)
                #pragma unroll
                for (int ni = 0; ni < 4; ni++)
                    mma16816h(acc[mi][ni], alf[mi], &bhf[ni >> 1][(ni & 1) << 1]);
        }
        __syncthreads();
    }

    const int g = lane >> 2, tq = lane & 3;
    #pragma unroll
    for (int mi = 0; mi < 2; mi++) {
        #pragma unroll
        for (int ni = 0; ni < 4; ni++) {
            #pragma unroll
            for (int half = 0; half < 2; half++) {
                int r = (wm << 5) + (mi << 4) + g + half * 8;
                int c = (wn << 5) + (ni << 3) + (tq << 1);
                float v0 = acc[mi][ni][half * 2], v1 = acc[mi][ni][half * 2 + 1];
                int m = m0 + r, n = n0 + c;
                if (mode == 3) {
                    *(float2*)&outp[(size_t)m * 1024 + n] = make_float2(v0, v1);
                } else {
                    int b = m >> 11, s = m & 2047, hd = n >> 6, dk = n & 63;
                    size_t o = (((size_t)(b * 16 + hd) * 2048) + s) * 64 + dk;
                    uint32_t hv = h2(v0, v1);
                    __half* d = (mode == 0) ? g_Q16 : (mode == 1) ? g_K16 : g_V16;
                    *(uint32_t*)(d + o) = hv;
                }
            }
        }
    }
}

// ---------------- fused attention: 128q-tile, two-pass, mod-3 ring -------------
// 16 warps: wm=wid>>1 (q 16-row slice of 128), wn=wid&1 (k 64-col slice of 128)
// smem: Q16 0 (16K), rowsm 16384 (128f), rinv 16896 (128f),
//       bias s @ 17408+s*1024 (255f, 3 stages), mask s @ 20480+s*512 (3 stages),
//       K/V ring @ 22528 + (s%3)*32768: {K16 +0 (16K), V16 +16384 (16K)}
//       PV-reduce buffer (2 x 32KB) reuses 22528.. after last tile.
__global__ __launch_bounds__(512) void attn_fused(const int* __restrict__ mask,
                                                  float* __restrict__ attn) {
    extern __shared__ __align__(1024) char smx[];
    const uint32_t sb = smem_u32(smx);
    float* rowsm = (float*)(smx + 16384);
    float* rinv  = (float*)(smx + 16896);
    const int t = threadIdx.x, lane = t & 31, wid = t >> 5;
    const int wm = wid >> 1, wn = wid & 1;
    const int q0 = blockIdx.x << 7, bh = blockIdx.y, b = bh >> 4, h = bh & 15;
    const int g = lane >> 2, tq = lane & 3;

    // persistent Q tile (128 x 64), single fp16
    #pragma unroll
    for (int i = 0; i < 2; i++) {
        int idx = t + (i << 9);
        int row = idx >> 3, ge = (idx & 7) << 3;
        uint32_t so = swz(row * 128 + (ge << 1));
        size_t go = ((size_t)bh * 2048 + q0 + row) * 64 + ge;
        *(uint4*)(smx + so) = *(const uint4*)(g_Q16 + go);
    }
    if (t < 128) rowsm[t] = 0.f;
    __syncthreads();

    const uint32_t a_row = (lane & 7) + ((lane >> 3) & 1) * 8;
    const uint32_t a_kb  = (lane >> 4) * 16;
    const uint32_t b_row = (lane & 7) + (lane >> 4) * 8;
    const uint32_t b_kb  = ((lane >> 3) & 1) * 16;

    // lvl: 0 = K16 only (pass 1), 1 = K16+V16 (pass 2)
    auto issue = [&](int kt, int lvl) {
        const int k0 = kt << 7, s = kt % 3;
        const uint32_t stb = sb + 22528 + (uint32_t)s * 32768;
        #pragma unroll
        for (int i = 0; i < 2; i++) {
            int idx = t + (i << 9);
            int row = idx >> 3, ge = (idx & 7) << 3;
            uint32_t so = swz(row * 128 + (ge << 1));
            size_t go = ((size_t)bh * 2048 + k0 + row) * 64 + ge;
            cpa16(stb + so, g_K16 + go);
            if (lvl) cpa16(stb + 16384 + so, g_V16 + go);
        }
        CP_COMMIT();
        float* bw = (float*)(smx + 17408 + s * 1024);
        int*   ms = (int*)(smx + 20480 + s * 512);
        if (t < 255) bw[t] = g_bias[h * 4096 + (k0 - q0 + 1921) + t];
        if (t < 128) ms[t] = mask[b * 2048 + k0 + t];
    };

    // hoist this warp's Q fragments (16 q-rows, k-invariant)
    uint32_t qf[4][4];
    #pragma unroll
    for (int ki = 0; ki < 4; ki++) {
        uint32_t off = swz(((wm << 4) + a_row) * 128 + (ki << 5) + a_kb);
        ldsm4(qf[ki], sb + off);
    }

    // 1-term S compute: 16q x 64k per warp
    auto computeS = [&](int stage, float acc[8][4]) {
        const uint32_t kbb = sb + 22528 + (uint32_t)stage * 32768;
        #pragma unroll
        for (int ki = 0; ki < 4; ki++) {
            uint32_t bhf[4][4];
            #pragma unroll
            for (int nh = 0; nh < 4; nh++) {
                uint32_t off = swz(((wn << 6) + (nh << 4) + b_row) * 128 + (ki << 5) + b_kb);
                ldsm4(bhf[nh], kbb + off);
            }
            #pragma unroll
            for (int ni = 0; ni < 8; ni++)
                mma16816h(acc[ni], qf[ki], &bhf[ni >> 1][(ni & 1) << 1]);
        }
    };

    // ---------------- pass 1: row sums ----------------
    {
        float rowpart[2] = {};
        issue(0, 0); issue(1, 0);
        for (int kt = 0; kt < 16; kt++) {
            if (kt == 15) { CP_WAIT0(); } else { CP_WAIT1(); }
            __syncthreads();
            float acc[8][4] = {};
            computeS(kt % 3, acc);
            const float* bw = (const float*)(smx + 17408 + (kt % 3) * 1024);
            const int*   ms = (const int*)(smx + 20480 + (kt % 3) * 512);
            #pragma unroll
            for (int half = 0; half < 2; half++) {
                int r = (wm << 4) + g + half * 8;
                float rp = 0.f;
                #pragma unroll
                for (int ni = 0; ni < 8; ni++) {
                    int c = (wn << 6) + (ni << 3) + (tq << 1);
                    float s0 = fmaf(acc[ni][half * 2],     0.125f, bw[c - r + 127]);
                    float s1 = fmaf(acc[ni][half * 2 + 1], 0.125f, bw[c + 1 - r + 127]);
                    rp += (ms[c]     ? __expf(s0) : 0.f);
                    rp += (ms[c + 1] ? __expf(s1) : 0.f);
                }
                rowpart[half] += rp;
            }
            if (kt + 2 < 16) issue(kt + 2, 0);
        }
        #pragma unroll
        for (int half = 0; half < 2; half++) {
            float v = rowpart[half];
            v += __shfl_xor_sync(0xffffffffu, v, 1);
            v += __shfl_xor_sync(0xffffffffu, v, 2);
            if (tq == 0)
                atomicAdd(&rowsm[(wm << 4) + g + half * 8], v);
        }
    }
    __syncthreads();
    if (t < 128) rinv[t] = 1.0f / rowsm[t];
    __syncthreads();
    float riv[2];
    #pragma unroll
    for (int half = 0; half < 2; half++)
        riv[half] = rinv[(wm << 4) + g + half * 8];

    // ---------------- pass 2: normalized attn store + fp16 PV -----------------
    float pv[8][4] = {};
    issue(0, 1); issue(1, 1);
    for (int kt = 0; kt < 16; kt++) {
        const int k0 = kt << 7;
        if (kt == 15) { CP_WAIT0(); } else { CP_WAIT1(); }
        __syncthreads();
        float acc[8][4] = {};
        computeS(kt % 3, acc);
        const float* bw = (const float*)(smx + 17408 + (kt % 3) * 1024);
        const int*   ms = (const int*)(smx + 20480 + (kt % 3) * 512);
        #pragma unroll
        for (int half = 0; half < 2; half++) {
            int r = (wm << 4) + g + half * 8;
            float ri = riv[half];
            #pragma unroll
            for (int ni = 0; ni < 8; ni++) {
                int c = (wn << 6) + (ni << 3) + (tq << 1);
                float s0 = fmaf(acc[ni][half * 2],     0.125f, bw[c - r + 127]);
                float s1 = fmaf(acc[ni][half * 2 + 1], 0.125f, bw[c + 1 - r + 127]);
                float e0 = (ms[c]     ? __expf(s0) : 0.f) * ri;
                float e1 = (ms[c + 1] ? __expf(s1) : 0.f) * ri;
                *(float2*)&attn[((size_t)bh * 2048 + q0 + r) * 2048 + k0 + c] =
                    make_float2(e0, e1);
                acc[ni][half * 2]     = e0;
                acc[ni][half * 2 + 1] = e1;
            }
        }
        // PV: P (fp16, this warp's 16q x 64k) x V (fp16, its 64k x 64dv)
        const uint32_t vbase = sb + 22528 + (uint32_t)(kt % 3) * 32768 + 16384;
        #pragma unroll
        for (int j = 0; j < 4; j++) {             // k16 groups within 64k slice
            uint32_t Ahh[4];
            Ahh[0] = h2(acc[2*j][0],   acc[2*j][1]);
            Ahh[1] = h2(acc[2*j][2],   acc[2*j][3]);
            Ahh[2] = h2(acc[2*j+1][0], acc[2*j+1][1]);
            Ahh[3] = h2(acc[2*j+1][2], acc[2*j+1][3]);
            #pragma unroll
            for (int dvg = 0; dvg < 4; dvg++) {
                uint32_t vf[4];
                uint32_t off = swz(((wn << 6) + (j << 4) + a_row) * 128 + (dvg << 5) + a_kb);
                ldsm4t(vf, vbase + off);
                #pragma unroll
                for (int n8 = 0; n8 < 2; n8++)
                    mma16816h(pv[dvg * 2 + n8], Ahh, &vf[n8 << 1]);
            }
        }
        if (kt + 2 < 16) issue(kt + 2, 1);
    }

    // ---------------- cross-warp (wn) PV reduction + ctx store (fp16 hi/lo) ----
    __syncthreads();                                // all ring reads done
    #pragma unroll
    for (int ni = 0; ni < 8; ni++)
        #pragma unroll
        for (int half = 0; half < 2; half++) {
            int row = (wm << 4) + g + half * 8;
            uint32_t off = 22528 + (uint32_t)wn * 32768 + row * 256 + ((ni << 3) + (tq << 1)) * 4;
            *(float2*)(smx + off) = make_float2(pv[ni][half * 2], pv[ni][half * 2 + 1]);
        }
    __syncthreads();
    #pragma unroll
    for (int i = 0; i < 8; i++) {
        int idx = t + (i << 9);
        int row = idx >> 5, dvp = idx & 31;
        float2 v0 = *(float2*)(smx + 22528 + row * 256 + dvp * 8);
        float2 v1 = *(float2*)(smx + 22528 + 32768 + row * 256 + dvp * 8);
        float sx = v0.x + v1.x, sy = v0.y + v1.y;
        uint32_t lo, hi = pkh2(sx, sy, lo);
        size_t o = ((size_t)(b * 2048 + q0 + row)) * 1024 + (h << 6) + dvp * 2;
        *(uint32_t*)(g_Ch + o) = hi;
        *(uint32_t*)(g_Cl + o) = lo;
    }
}

// ---------------- launch --------------------------------------------------------
#define PROJ_SMEM 98304
#define ATT_SMEM  120832

extern "C" void kernel_launch(void* const* d_in, const int* in_sizes, int n_in,
                              void* d_out, int out_size) {
    const float* hs   = (const float*)d_in[0];
    const int*   mask = (const int*)d_in[1];
    const float* Wq   = (const float*)d_in[2];
    const float* Wk   = (const float*)d_in[3];
    const float* Wv   = (const float*)d_in[4];
    const float* Wo   = (const float*)d_in[5];
    const float* rb   = (const float*)d_in[6];
    float* out  = (float*)d_out;
    float* attn = out + 4194304;

    cudaFuncSetAttribute(proj_gemm,  cudaFuncAttributeMaxDynamicSharedMemorySize, PROJ_SMEM);
    cudaFuncSetAttribute(attn_fused, cudaFuncAttributeMaxDynamicSharedMemorySize, ATT_SMEM);

    bias_init<<<16, 256>>>(rb);
    split_x<<<4096, 256>>>(hs);
    wsplit<<<dim3(32, 32, 4), dim3(32, 8)>>>(Wq, Wk, Wv, Wo);

    proj_gemm<<<dim3(8, 32, 3), 512, PROJ_SMEM>>>(nullptr, 1);   // Q,K,V fused

    attn_fused<<<dim3(16, 32), 512, ATT_SMEM>>>(mask, attn);     // softmax+attn+ctx

    proj_gemm<<<dim3(8, 32, 1), 512, PROJ_SMEM>>>(out, 0);       // ctx @ Wo
}